// round 15
// baseline (speedup 1.0000x reference)
#include <cuda_runtime.h>
#include <cuda_fp16.h>
#include <cstdint>

#define BB 64
#define NN 4096
#define DD 128
#define NS 8
#define SCALE 0.08838834764831845f

// ---------------- device scratch ----------------
__device__ __half g_xn[BB*NN*DD];     // 67 MB fp16 normalized input
__device__ float g_qk[BB*NS*DD];
__device__ float g_lb[BB*NS];
__device__ float g_slots[BB*NS*DD];
__device__ float g_y[BB*NS*DD];
__device__ float g_rs[BB*NS];
__device__ float g_wkT[DD*DD];
__device__ int   g_cnt[BB];           // zero-initialized; reset by consumer

__device__ __forceinline__ uint32_t smem_u32(const void* p){
    uint32_t a;
    asm("{ .reg .u64 t; cvta.to.shared.u64 t, %1; cvt.u32.u64 %0, t; }" : "=r"(a) : "l"(p));
    return a;
}
#define LDSM4(r0,r1,r2,r3,addr) \
    asm volatile("ldmatrix.sync.aligned.m8n8.x4.shared.b16 {%0,%1,%2,%3}, [%4];" \
        : "=r"(r0),"=r"(r1),"=r"(r2),"=r"(r3) : "r"(addr))
#define LDSM2(r0,r1,addr) \
    asm volatile("ldmatrix.sync.aligned.m8n8.x2.shared.b16 {%0,%1}, [%2];" \
        : "=r"(r0),"=r"(r1) : "r"(addr))
#define LDSM2T(r0,r1,addr) \
    asm volatile("ldmatrix.sync.aligned.m8n8.x2.trans.shared.b16 {%0,%1}, [%2];" \
        : "=r"(r0),"=r"(r1) : "r"(addr))
#define MMAF16(c,a0,a1,a2,a3,b0,b1) \
    asm volatile("mma.sync.aligned.m16n8k16.row.col.f32.f16.f16.f32 " \
        "{%0,%1,%2,%3}, {%4,%5,%6,%7}, {%8,%9}, {%0,%1,%2,%3};" \
        : "+f"((c)[0]),"+f"((c)[1]),"+f"((c)[2]),"+f"((c)[3]) \
        : "r"(a0),"r"(a1),"r"(a2),"r"(a3),"r"(b0),"r"(b1))

// smem layout (bytes) — 256-token tile
#define SM_QKHI 0
#define SM_QKLO 2176
#define SM_LB   4352
#define SM_LG   4384                   // 256 x 10 floats
#define SM_PA   14624                  // 16 x 264 halfs (pitch 528B)
#define SM_XN   23072                  // 256 x 136 halfs (pitch 272B); reused by tail
#define SM_TOT  92704

__global__ __launch_bounds__(256) void prep_wkT_kernel(const float* __restrict__ Wk){
    int i = blockIdx.x*256 + threadIdx.x;
    int d = i >> 7, j = i & 127;
    g_wkT[d*128 + j] = Wk[j*128 + d];
}

// ---------------- init: slots, zero accums, qk0 + lb0 ----------------
__global__ __launch_bounds__(128) void init_q_kernel(
    const float* __restrict__ si,
    const float* __restrict__ Wq, const float* __restrict__ bq,
    const float* __restrict__ gs, const float* __restrict__ bs,
    const float* __restrict__ bk)
{
    __shared__ float sn[128];
    __shared__ float sq[128];
    __shared__ float red[8];
    const int row = blockIdx.x, tid = threadIdx.x;
    const int lane = tid & 31, wrp = tid >> 5;
    float v = si[row*128 + tid];
    g_slots[row*128 + tid] = v;
    g_y[row*128 + tid] = 0.f;
    if (tid == 0) g_rs[row] = 0.f;
    float s = v, ss = v*v;
    #pragma unroll
    for (int o = 16; o; o >>= 1){
        s  += __shfl_xor_sync(0xffffffffu, s, o);
        ss += __shfl_xor_sync(0xffffffffu, ss, o);
    }
    if (lane == 0){ red[wrp] = s; red[4+wrp] = ss; }
    __syncthreads();
    s  = red[0]+red[1]+red[2]+red[3];
    ss = red[4]+red[5]+red[6]+red[7];
    float m = s*(1.f/128.f);
    float rstd = rsqrtf(ss*(1.f/128.f) - m*m + 1e-5f);
    sn[tid] = (v - m)*rstd*gs[tid] + bs[tid];
    __syncthreads();
    float acc = bq[tid];
    {
        const float4* wr  = (const float4*)(Wq + tid*128);
        const float4* sn4 = (const float4*)sn;
        #pragma unroll
        for (int e = 0; e < 32; e++){
            float4 w = wr[e], q = sn4[e];
            acc += w.x*q.x + w.y*q.y + w.z*q.z + w.w*q.w;
        }
    }
    sq[tid] = acc * SCALE;
    __syncthreads();
    float qk = 0.f;
    {
        const float4* wr  = (const float4*)(g_wkT + tid*128);
        const float4* sq4 = (const float4*)sq;
        #pragma unroll
        for (int e = 0; e < 32; e++){
            float4 w = wr[e], q = sq4[e];
            qk += w.x*q.x + w.y*q.y + w.z*q.z + w.w*q.w;
        }
    }
    g_qk[row*128 + tid] = qk;
    float p = sq[tid] * bk[tid];
    #pragma unroll
    for (int o = 16; o; o >>= 1) p += __shfl_xor_sync(0xffffffffu, p, o);
    __syncthreads();
    if (lane == 0) red[wrp] = p;
    __syncthreads();
    if (tid == 0) g_lb[row] = red[0]+red[1]+red[2]+red[3];
}

// ---------------- 8-row GEMV helper: r = tid>>1, qh = tid&1 (half-K) ----------------
__device__ __forceinline__ void gemv8(const float* __restrict__ W,
                                      const float (* __restrict__ xin)[128],
                                      float* __restrict__ p, int r, int qh)
{
    const float4* w = (const float4*)(W + r*128);
    #pragma unroll
    for (int j = 0; j < 8; j++) p[j] = 0.f;
    #pragma unroll
    for (int e = 0; e < 16; e++){
        float4 wv = w[qh + e*2];
        #pragma unroll
        for (int j = 0; j < 8; j++){
            float4 a = ((const float4*)xin[j])[qh + e*2];
            p[j] += wv.x*a.x + wv.y*a.y + wv.z*a.z + wv.w*a.w;
        }
    }
    #pragma unroll
    for (int j = 0; j < 8; j++) p[j] += __shfl_xor_sync(0xffffffffu, p[j], 1);
}

// ---------------- fused per-iteration kernel: attn + (last CTA per batch) GRU tail ----------------
// 256 threads (8 warps), 256 tokens per CTA; grid = B * 16
__global__ __launch_bounds__(256) void fused_iter_kernel(
    const float* __restrict__ xin,              // non-null -> iter 0: inline LN
    const float* __restrict__ gin, const float* __restrict__ bin,
    const float* __restrict__ W_ih, const float* __restrict__ W_hh,
    const float* __restrict__ b_ih, const float* __restrict__ b_hh,
    const float* __restrict__ gm, const float* __restrict__ bm,
    const float* __restrict__ W1, const float* __restrict__ b1,
    const float* __restrict__ W2, const float* __restrict__ b2,
    const float* __restrict__ Wq, const float* __restrict__ bq,
    const float* __restrict__ gs, const float* __restrict__ bs,
    const float* __restrict__ Wv, const float* __restrict__ bv,
    const float* __restrict__ bk,
    float* __restrict__ out)                    // non-null on final iteration
{
    extern __shared__ __align__(16) char smem[];
    const uint32_t sb = smem_u32(smem);
    const int tid = threadIdx.x;
    const int wid = tid >> 5, lane = tid & 31;
    const int bb = blockIdx.x >> 4;
    const int n0 = (blockIdx.x & 15) * 256;

    // ---- stage qk hi/lo + lb ----
    #pragma unroll
    for (int i = 0; i < 4; i++){
        int idx = tid + i*256;
        int s = idx >> 7, d = idx & 127;
        float v = g_qk[bb*1024 + idx];
        __half h = __float2half_rn(v);
        __half l = __float2half_rn(v - __half2float(h));
        *(__half*)(smem + SM_QKHI + s*272 + d*2) = h;
        *(__half*)(smem + SM_QKLO + s*272 + d*2) = l;
    }
    if (tid < 8) ((float*)(smem + SM_LB))[tid] = g_lb[bb*8 + tid];

    // ---- stage xn tile (256 x 128 halfs, pitch 272B) ----
    if (xin){
        const float* gx = xin + (size_t)(bb*4096 + n0)*128;
        float4 g4 = ((const float4*)gin)[lane];
        float4 b4 = ((const float4*)bin)[lane];
        #pragma unroll 1
        for (int rr = 0; rr < 32; rr += 4){
            float4 v[4];
            #pragma unroll
            for (int u = 0; u < 4; u++)
                v[u] = ((const float4*)(gx + (size_t)(wid*32 + rr + u)*128))[lane];
            #pragma unroll
            for (int u = 0; u < 4; u++){
                const int row = wid*32 + rr + u;
                float s  = v[u].x + v[u].y + v[u].z + v[u].w;
                float ss = v[u].x*v[u].x + v[u].y*v[u].y + v[u].z*v[u].z + v[u].w*v[u].w;
                #pragma unroll
                for (int o = 16; o; o >>= 1){
                    s  += __shfl_xor_sync(0xffffffffu, s, o);
                    ss += __shfl_xor_sync(0xffffffffu, ss, o);
                }
                const float m = s * (1.f/128.f);
                const float rstd = rsqrtf(ss*(1.f/128.f) - m*m + 1e-5f);
                float y0 = (v[u].x - m)*rstd*g4.x + b4.x;
                float y1 = (v[u].y - m)*rstd*g4.y + b4.y;
                float y2 = (v[u].z - m)*rstd*g4.z + b4.z;
                float y3 = (v[u].w - m)*rstd*g4.w + b4.w;
                __half2 h01 = __floats2half2_rn(y0, y1);
                __half2 h23 = __floats2half2_rn(y2, y3);
                uint2 uu;
                uu.x = *(uint32_t*)&h01;
                uu.y = *(uint32_t*)&h23;
                *(uint2*)(smem + SM_XN + row*272 + lane*8) = uu;
                *(uint2*)(g_xn + (size_t)(bb*4096 + n0 + row)*128 + lane*4) = uu;
            }
        }
    } else {
        const __half* src = g_xn + (size_t)(bb*4096 + n0)*128;
        #pragma unroll
        for (int i = 0; i < 16; i++){
            int idx = tid + i*256;
            int r = idx >> 4, c = idx & 15;
            uint4 v = ((const uint4*)(src + (size_t)r*128))[c];
            *(uint4*)(smem + SM_XN + r*272 + c*16) = v;
        }
    }
    __syncthreads();

    // ---- phase 1: logits = xn @ qk^T (hi + lo) ----
    const int aRow  = (lane & 7) + ((lane >> 3) & 1) * 8;
    const int aKoff = (lane >> 4) * 16;
    {
        const int wbase = wid * 32;
        float c[2][4] = {{0.f,0.f,0.f,0.f},{0.f,0.f,0.f,0.f}};
        const uint32_t bAddrH = sb + SM_QKHI + (lane & 7)*272 + ((lane >> 3) & 1)*16;
        const uint32_t bAddrL = bAddrH + (SM_QKLO - SM_QKHI);
        #pragma unroll
        for (int k = 0; k < 8; k++){
            const uint32_t ko = k*32;
            uint32_t bh0,bh1, bl0,bl1;
            LDSM2(bh0,bh1, bAddrH + ko);
            LDSM2(bl0,bl1, bAddrL + ko);
            #pragma unroll
            for (int mt = 0; mt < 2; mt++){
                uint32_t a0,a1,a2,a3;
                LDSM4(a0,a1,a2,a3, sb + SM_XN + (wbase + mt*16 + aRow)*272 + aKoff + ko);
                MMAF16(c[mt], a0,a1,a2,a3, bh0,bh1);
                MMAF16(c[mt], a0,a1,a2,a3, bl0,bl1);
            }
        }
        #pragma unroll
        for (int mt = 0; mt < 2; mt++){
            const int row = wbase + mt*16 + (lane >> 2);
            const int col = (lane & 3) * 2;
            float2 v0; v0.x = c[mt][0]; v0.y = c[mt][1];
            float2 v1; v1.x = c[mt][2]; v1.y = c[mt][3];
            *(float2*)(smem + SM_LG + row*40 + col*4)     = v0;
            *(float2*)(smem + SM_LG + (row+8)*40 + col*4) = v1;
        }
    }
    __syncthreads();

    // ---- softmax (1 token per thread) -> pA hi/lo ----
    {
        const float* lbs = (const float*)(smem + SM_LB);
        const float* lg = (const float*)(smem + SM_LG + tid*40);
        float l[8];
        #pragma unroll
        for (int i = 0; i < 8; i++) l[i] = lg[i] + lbs[i];
        float mx = l[0];
        #pragma unroll
        for (int i = 1; i < 8; i++) mx = fmaxf(mx, l[i]);
        float sum = 0.f;
        #pragma unroll
        for (int i = 0; i < 8; i++){ l[i] = __expf(l[i]-mx); sum += l[i]; }
        float inv = 1.f/sum;
        #pragma unroll
        for (int i = 0; i < 8; i++){
            float p = l[i]*inv + 1e-8f;
            __half h = __float2half_rn(p);
            __half lo = __float2half_rn(p - __half2float(h));
            *(__half*)(smem + SM_PA + i*528 + tid*2)     = h;
            *(__half*)(smem + SM_PA + (i+8)*528 + tid*2) = lo;
        }
    }
    __syncthreads();

    // ---- rowsum: warp w reduces slot w ----
    {
        const __half2* hi = (const __half2*)(smem + SM_PA + wid*528);
        const __half2* lo = (const __half2*)(smem + SM_PA + (wid+8)*528);
        float r = 0.f;
        #pragma unroll
        for (int i = 0; i < 4; i++){
            float2 a = __half22float2(hi[lane + i*32]);
            float2 b = __half22float2(lo[lane + i*32]);
            r += a.x + a.y + b.x + b.y;
        }
        #pragma unroll
        for (int o = 16; o; o >>= 1) r += __shfl_xor_sync(0xffffffffu, r, o);
        if (lane == 0) atomicAdd(&g_rs[bb*8 + wid], r);
    }

    // ---- phase 2: y = p @ xn  (hi rows 0-7, lo rows 8-15, fold) ----
    {
        float c2[2][4] = {{0.f,0.f,0.f,0.f},{0.f,0.f,0.f,0.f}};
        const uint32_t aBase = sb + SM_PA + aRow*528 + aKoff;
        #pragma unroll
        for (int k = 0; k < 16; k++){
            uint32_t a0,a1,a2,a3;
            LDSM4(a0,a1,a2,a3, aBase + k*32);
            #pragma unroll
            for (int nt = 0; nt < 2; nt++){
                const int d_base = (wid*2 + nt)*8;
                uint32_t b0,b1;
                LDSM2T(b0,b1, sb + SM_XN + (k*16 + (lane & 15))*272 + d_base*2);
                MMAF16(c2[nt], a0,a1,a2,a3, b0,b1);
            }
        }
        const int slot = lane >> 2;
        #pragma unroll
        for (int nt = 0; nt < 2; nt++){
            const int col = (wid*2 + nt)*8 + (lane & 3)*2;
            atomicAdd(&g_y[(bb*8+slot)*128 + col],     c2[nt][0] + c2[nt][2]);
            atomicAdd(&g_y[(bb*8+slot)*128 + col + 1], c2[nt][1] + c2[nt][3]);
        }
    }

    // ================= tail: last CTA of this batch runs GRU+MLP+q =================
    __threadfence();
    __syncthreads();
    __shared__ int s_last;
    if (tid == 0){
        int old = atomicAdd(&g_cnt[bb], 1);
        s_last = (old == 15) ? 1 : 0;
        if (old == 15) g_cnt[bb] = 0;          // reset for next launch
    }
    __syncthreads();
    if (!s_last) return;

    // tail smem overlays (reuse xn region, 40KB of 69KB)
    float (*sx)[128]  = (float(*)[128])(smem + SM_XN);
    float (*sh)[128]  = sx + 8;
    float (*su)[128]  = sh + 8;
    float (*shn)[128] = su + 8;
    float (*sgi)[128] = shn + 8;               // 24 rows (3 gates x 8)
    float (*sgh)[128] = sgi + 24;              // 24 rows
    __shared__ float red_s[8][4], red_ss[8][4];

    const int r8 = tid >> 1, qh = tid & 1;
    const int g8 = tid >> 7, d8 = tid & 127;
    const int wIn8 = (tid >> 5) & 3;
    const int r0 = bb * 8;

    // stage y/rs/slots (read rs for all rows BEFORE zeroing)
    float rsv4[4];
    #pragma unroll
    for (int it = 0; it < 4; it++) rsv4[it] = g_rs[r0 + 2*it + g8];
    #pragma unroll
    for (int it = 0; it < 4; it++){
        const int j = 2*it + g8;
        sx[j][d8] = g_y[(r0+j)*128 + d8] / rsv4[it];
        sh[j][d8] = g_slots[(r0+j)*128 + d8];
        g_y[(r0+j)*128 + d8] = 0.f;
    }
    __syncthreads();
    if (tid < 8) g_rs[r0 + tid] = 0.f;

    float p8[8];

    // u = Wv @ sx + bv ; gh = W_hh @ sh (independent, sequential issue)
    gemv8(Wv, sx, p8, r8, qh);
    if (qh == 0){
        const float b = bv[r8];
        #pragma unroll
        for (int j = 0; j < 8; j++) su[j][r8] = b + p8[j];
    }
    #pragma unroll 1
    for (int g = 0; g < 3; g++){
        gemv8(W_hh + g*16384, sh, p8, r8, qh);
        if (qh == 0){
            const float b = b_hh[g*128 + r8];
            #pragma unroll
            for (int j = 0; j < 8; j++) sgh[g*8 + j][r8] = b + p8[j];
        }
    }
    __syncthreads();

    // gi = W_ih @ u
    #pragma unroll 1
    for (int g = 0; g < 3; g++){
        gemv8(W_ih + g*16384, su, p8, r8, qh);
        if (qh == 0){
            const float b = b_ih[g*128 + r8];
            #pragma unroll
            for (int j = 0; j < 8; j++) sgi[g*8 + j][r8] = b + p8[j];
        }
    }
    __syncthreads();

    // hn + LN(hn) -> sx
    float hn4[4];
    #pragma unroll
    for (int it = 0; it < 4; it++){
        const int j = 2*it + g8;
        float rr = 1.f/(1.f + __expf(-(sgi[j][d8] + sgh[j][d8])));
        float z  = 1.f/(1.f + __expf(-(sgi[8+j][d8] + sgh[8+j][d8])));
        float n  = tanhf(sgi[16+j][d8] + rr*sgh[16+j][d8]);
        float hn = (1.f - z)*n + z*sh[j][d8];
        hn4[it] = hn;
        shn[j][d8] = hn;
        float s = hn, ss = hn*hn;
        #pragma unroll
        for (int o = 16; o; o >>= 1){
            s  += __shfl_xor_sync(0xffffffffu, s, o);
            ss += __shfl_xor_sync(0xffffffffu, ss, o);
        }
        if ((tid & 31) == 0){ red_s[j][wIn8] = s; red_ss[j][wIn8] = ss; }
    }
    __syncthreads();
    #pragma unroll
    for (int it = 0; it < 4; it++){
        const int j = 2*it + g8;
        float s  = red_s[j][0]+red_s[j][1]+red_s[j][2]+red_s[j][3];
        float ss = red_ss[j][0]+red_ss[j][1]+red_ss[j][2]+red_ss[j][3];
        float m = s*(1.f/128.f);
        float rstd = rsqrtf(ss*(1.f/128.f) - m*m + 1e-5f);
        sx[j][d8] = (hn4[it] - m)*rstd*gm[d8] + bm[d8];
    }
    __syncthreads();

    // MLP layer 1 (relu) -> su
    gemv8(W1, sx, p8, r8, qh);
    if (qh == 0){
        const float b = b1[r8];
        #pragma unroll
        for (int j = 0; j < 8; j++) su[j][r8] = fmaxf(b + p8[j], 0.f);
    }
    __syncthreads();

    // MLP layer 2 + residual -> sgh(reuse), g_slots, (out)
    gemv8(W2, su, p8, r8, qh);
    if (qh == 0){
        const float b = b2[r8];
        #pragma unroll
        for (int j = 0; j < 8; j++){
            float o = shn[j][r8] + b + p8[j];
            sgh[j][r8] = o;
            g_slots[(r0+j)*128 + r8] = o;
            if (out) out[(r0+j)*128 + r8] = o;
        }
    }
    __syncthreads();

    // LN(out) -> sx
    float ov4[4];
    #pragma unroll
    for (int it = 0; it < 4; it++){
        const int j = 2*it + g8;
        float ov = sgh[j][d8];
        ov4[it] = ov;
        float s = ov, ss = ov*ov;
        #pragma unroll
        for (int o = 16; o; o >>= 1){
            s  += __shfl_xor_sync(0xffffffffu, s, o);
            ss += __shfl_xor_sync(0xffffffffu, ss, o);
        }
        if ((tid & 31) == 0){ red_s[j][wIn8] = s; red_ss[j][wIn8] = ss; }
    }
    __syncthreads();
    #pragma unroll
    for (int it = 0; it < 4; it++){
        const int j = 2*it + g8;
        float s  = red_s[j][0]+red_s[j][1]+red_s[j][2]+red_s[j][3];
        float ss = red_ss[j][0]+red_ss[j][1]+red_ss[j][2]+red_ss[j][3];
        float m = s*(1.f/128.f);
        float rstd = rsqrtf(ss*(1.f/128.f) - m*m + 1e-5f);
        sx[j][d8] = (ov4[it] - m)*rstd*gs[d8] + bs[d8];
    }
    __syncthreads();

    // q projection (scaled) -> su
    gemv8(Wq, sx, p8, r8, qh);
    if (qh == 0){
        const float b = bq[r8];
        #pragma unroll
        for (int j = 0; j < 8; j++) su[j][r8] = (b + p8[j]) * SCALE;
    }
    __syncthreads();

    // qk = wkT @ sq -> g_qk ; lb = sq . bk -> g_lb
    gemv8(g_wkT, su, p8, r8, qh);
    if (qh == 0){
        #pragma unroll
        for (int j = 0; j < 8; j++) g_qk[(r0+j)*128 + r8] = p8[j];
    }
    #pragma unroll
    for (int it = 0; it < 4; it++){
        const int j = 2*it + g8;
        float pb = su[j][d8] * bk[d8];
        #pragma unroll
        for (int o = 16; o; o >>= 1) pb += __shfl_xor_sync(0xffffffffu, pb, o);
        if ((tid & 31) == 0) red_s[j][wIn8] = pb;
    }
    __syncthreads();
    if (tid < 8)
        g_lb[r0 + tid] = red_s[tid][0]+red_s[tid][1]+red_s[tid][2]+red_s[tid][3];
}

// ---------------- launch ----------------
extern "C" void kernel_launch(void* const* d_in, const int* in_sizes, int n_in,
                              void* d_out, int out_size)
{
    const float* x    = (const float*)d_in[0];
    const float* si   = (const float*)d_in[1];
    const float* Wq   = (const float*)d_in[2];
    const float* bq   = (const float*)d_in[3];
    const float* Wk   = (const float*)d_in[4];
    const float* bk   = (const float*)d_in[5];
    const float* Wv   = (const float*)d_in[6];
    const float* bv   = (const float*)d_in[7];
    const float* gin  = (const float*)d_in[8];
    const float* bin  = (const float*)d_in[9];
    const float* gsl  = (const float*)d_in[10];
    const float* bsl  = (const float*)d_in[11];
    const float* gm   = (const float*)d_in[12];
    const float* bm   = (const float*)d_in[13];
    const float* W1   = (const float*)d_in[14];
    const float* b1   = (const float*)d_in[15];
    const float* W2   = (const float*)d_in[16];
    const float* b2   = (const float*)d_in[17];
    const float* W_ih = (const float*)d_in[18];
    const float* W_hh = (const float*)d_in[19];
    const float* b_ih = (const float*)d_in[20];
    const float* b_hh = (const float*)d_in[21];

    static bool attr_set = false;
    if (!attr_set){
        cudaFuncSetAttribute(fused_iter_kernel,
                             cudaFuncAttributeMaxDynamicSharedMemorySize, SM_TOT);
        attr_set = true;
    }

    prep_wkT_kernel<<<64, 256>>>(Wk);
    init_q_kernel<<<512, 128>>>(si, Wq, bq, gsl, bsl, bk);
    for (int it = 0; it < 3; it++){
        fused_iter_kernel<<<1024, 256, SM_TOT>>>(
            it == 0 ? x : nullptr, gin, bin,
            W_ih, W_hh, b_ih, b_hh, gm, bm, W1, b1, W2, b2,
            Wq, bq, gsl, bsl, Wv, bv, bk,
            it == 2 ? (float*)d_out : nullptr);
    }
}

// round 16
// speedup vs baseline: 1.8273x; 1.8273x over previous
#include <cuda_runtime.h>
#include <cuda_fp16.h>
#include <cstdint>

#define BB 64
#define NN 4096
#define DD 128
#define NS 8
#define SCALE 0.08838834764831845f

// ---------------- device scratch ----------------
__device__ __half g_xn[BB*NN*DD];     // 67 MB fp16 normalized input
__device__ float g_qk[BB*NS*DD];
__device__ float g_lb[BB*NS];
__device__ float g_slots[BB*NS*DD];
__device__ float g_y[BB*NS*DD];
__device__ float g_rs[BB*NS];
__device__ float g_wkT[DD*DD];
// fp16 weight bundle for the GRU/MLP/q kernel
#define WV_OFF  0
#define WHH_OFF 16384
#define WIH_OFF 65536
#define W1_OFF  114688
#define W2_OFF  131072
#define WQ_OFF  147456
#define WKT_OFF 163840
#define WH_TOT  180224
__device__ __half g_wh[WH_TOT];

__device__ __forceinline__ uint32_t smem_u32(const void* p){
    uint32_t a;
    asm("{ .reg .u64 t; cvta.to.shared.u64 t, %1; cvt.u32.u64 %0, t; }" : "=r"(a) : "l"(p));
    return a;
}
#define LDSM4(r0,r1,r2,r3,addr) \
    asm volatile("ldmatrix.sync.aligned.m8n8.x4.shared.b16 {%0,%1,%2,%3}, [%4];" \
        : "=r"(r0),"=r"(r1),"=r"(r2),"=r"(r3) : "r"(addr))
#define LDSM2(r0,r1,addr) \
    asm volatile("ldmatrix.sync.aligned.m8n8.x2.shared.b16 {%0,%1}, [%2];" \
        : "=r"(r0),"=r"(r1) : "r"(addr))
#define LDSM2T(r0,r1,addr) \
    asm volatile("ldmatrix.sync.aligned.m8n8.x2.trans.shared.b16 {%0,%1}, [%2];" \
        : "=r"(r0),"=r"(r1) : "r"(addr))
#define MMAF16(c,a0,a1,a2,a3,b0,b1) \
    asm volatile("mma.sync.aligned.m16n8k16.row.col.f32.f16.f16.f32 " \
        "{%0,%1,%2,%3}, {%4,%5,%6,%7}, {%8,%9}, {%0,%1,%2,%3};" \
        : "+f"((c)[0]),"+f"((c)[1]),"+f"((c)[2]),"+f"((c)[3]) \
        : "r"(a0),"r"(a1),"r"(a2),"r"(a3),"r"(b0),"r"(b1))

// smem layout (bytes) — 256-token tile
#define SM_QKHI 0
#define SM_QKLO 2176
#define SM_LB   4352
#define SM_LG   4384                   // 256 x 10 floats
#define SM_PA   14624                  // 16 x 264 halfs (pitch 528B)
#define SM_XN   23072                  // 256 x 136 halfs (pitch 272B)
#define SM_TOT  92704

// ---------------- prep: fp16 weight bundle + fp32 wkT ----------------
__global__ __launch_bounds__(256) void prep_weights_kernel(
    const float* __restrict__ Wk, const float* __restrict__ Wv,
    const float* __restrict__ W_hh, const float* __restrict__ W_ih,
    const float* __restrict__ W1, const float* __restrict__ W2,
    const float* __restrict__ Wq)
{
    int i = blockIdx.x*256 + threadIdx.x;     // 0..180223
    float v;
    if (i < WHH_OFF)                v = Wv[i];
    else if (i < WIH_OFF)           v = W_hh[i - WHH_OFF];
    else if (i < W1_OFF)            v = W_ih[i - WIH_OFF];
    else if (i < W2_OFF)            v = W1[i - W1_OFF];
    else if (i < WQ_OFF)            v = W2[i - W2_OFF];
    else if (i < WKT_OFF)           v = Wq[i - WQ_OFF];
    else {
        int idx = i - WKT_OFF;
        int d = idx >> 7, j = idx & 127;
        v = Wk[j*128 + d];
        g_wkT[idx] = v;
    }
    g_wh[i] = __float2half_rn(v);
}

// ---------------- init: slots, zero accums, qk0 + lb0 ----------------
__global__ __launch_bounds__(128) void init_q_kernel(
    const float* __restrict__ si,
    const float* __restrict__ Wq, const float* __restrict__ bq,
    const float* __restrict__ gs, const float* __restrict__ bs,
    const float* __restrict__ bk)
{
    __shared__ float sn[128];
    __shared__ float sq[128];
    __shared__ float red[8];
    const int row = blockIdx.x, tid = threadIdx.x;
    const int lane = tid & 31, wrp = tid >> 5;
    float v = si[row*128 + tid];
    g_slots[row*128 + tid] = v;
    g_y[row*128 + tid] = 0.f;
    if (tid == 0) g_rs[row] = 0.f;
    float s = v, ss = v*v;
    #pragma unroll
    for (int o = 16; o; o >>= 1){
        s  += __shfl_xor_sync(0xffffffffu, s, o);
        ss += __shfl_xor_sync(0xffffffffu, ss, o);
    }
    if (lane == 0){ red[wrp] = s; red[4+wrp] = ss; }
    __syncthreads();
    s  = red[0]+red[1]+red[2]+red[3];
    ss = red[4]+red[5]+red[6]+red[7];
    float m = s*(1.f/128.f);
    float rstd = rsqrtf(ss*(1.f/128.f) - m*m + 1e-5f);
    sn[tid] = (v - m)*rstd*gs[tid] + bs[tid];
    __syncthreads();
    float acc = bq[tid];
    {
        const float4* wr  = (const float4*)(Wq + tid*128);
        const float4* sn4 = (const float4*)sn;
        #pragma unroll
        for (int e = 0; e < 32; e++){
            float4 w = wr[e], q = sn4[e];
            acc += w.x*q.x + w.y*q.y + w.z*q.z + w.w*q.w;
        }
    }
    sq[tid] = acc * SCALE;
    __syncthreads();
    float qk = 0.f;
    {
        const float4* wr  = (const float4*)(g_wkT + tid*128);
        const float4* sq4 = (const float4*)sq;
        #pragma unroll
        for (int e = 0; e < 32; e++){
            float4 w = wr[e], q = sq4[e];
            qk += w.x*q.x + w.y*q.y + w.z*q.z + w.w*q.w;
        }
    }
    g_qk[row*128 + tid] = qk;
    float p = sq[tid] * bk[tid];
    #pragma unroll
    for (int o = 16; o; o >>= 1) p += __shfl_xor_sync(0xffffffffu, p, o);
    __syncthreads();
    if (lane == 0) red[wrp] = p;
    __syncthreads();
    if (tid == 0) g_lb[row] = red[0]+red[1]+red[2]+red[3];
}

// ---------------- kernel 3: MMA attn (256-token tile) with optional inline LN ----------------
// 256 threads (8 warps), 256 tokens per block; grid = B * 16
__global__ __launch_bounds__(256) void fused_attn_mma_kernel(
    const float* __restrict__ xin,              // non-null -> iter 0: inline LN
    const float* __restrict__ gin, const float* __restrict__ bin)
{
    extern __shared__ __align__(16) char smem[];
    const uint32_t sb = smem_u32(smem);
    const int tid = threadIdx.x;
    const int wid = tid >> 5, lane = tid & 31;
    const int bb = blockIdx.x >> 4;
    const int n0 = (blockIdx.x & 15) * 256;

    // ---- stage qk hi/lo + lb ----
    #pragma unroll
    for (int i = 0; i < 4; i++){
        int idx = tid + i*256;
        int s = idx >> 7, d = idx & 127;
        float v = g_qk[bb*1024 + idx];
        __half h = __float2half_rn(v);
        __half l = __float2half_rn(v - __half2float(h));
        *(__half*)(smem + SM_QKHI + s*272 + d*2) = h;
        *(__half*)(smem + SM_QKLO + s*272 + d*2) = l;
    }
    if (tid < 8) ((float*)(smem + SM_LB))[tid] = g_lb[bb*8 + tid];

    // ---- stage xn tile (256 x 128 halfs, pitch 272B) ----
    if (xin){
        const float* gx = xin + (size_t)(bb*4096 + n0)*128;
        float4 g4 = ((const float4*)gin)[lane];
        float4 b4 = ((const float4*)bin)[lane];
        #pragma unroll 1
        for (int rr = 0; rr < 32; rr += 4){
            float4 v[4];
            #pragma unroll
            for (int u = 0; u < 4; u++)
                v[u] = ((const float4*)(gx + (size_t)(wid*32 + rr + u)*128))[lane];
            #pragma unroll
            for (int u = 0; u < 4; u++){
                const int row = wid*32 + rr + u;
                float s  = v[u].x + v[u].y + v[u].z + v[u].w;
                float ss = v[u].x*v[u].x + v[u].y*v[u].y + v[u].z*v[u].z + v[u].w*v[u].w;
                #pragma unroll
                for (int o = 16; o; o >>= 1){
                    s  += __shfl_xor_sync(0xffffffffu, s, o);
                    ss += __shfl_xor_sync(0xffffffffu, ss, o);
                }
                const float m = s * (1.f/128.f);
                const float rstd = rsqrtf(ss*(1.f/128.f) - m*m + 1e-5f);
                float y0 = (v[u].x - m)*rstd*g4.x + b4.x;
                float y1 = (v[u].y - m)*rstd*g4.y + b4.y;
                float y2 = (v[u].z - m)*rstd*g4.z + b4.z;
                float y3 = (v[u].w - m)*rstd*g4.w + b4.w;
                __half2 h01 = __floats2half2_rn(y0, y1);
                __half2 h23 = __floats2half2_rn(y2, y3);
                uint2 uu;
                uu.x = *(uint32_t*)&h01;
                uu.y = *(uint32_t*)&h23;
                *(uint2*)(smem + SM_XN + row*272 + lane*8) = uu;
                *(uint2*)(g_xn + (size_t)(bb*4096 + n0 + row)*128 + lane*4) = uu;
            }
        }
    } else {
        const __half* src = g_xn + (size_t)(bb*4096 + n0)*128;
        #pragma unroll
        for (int i = 0; i < 16; i++){
            int idx = tid + i*256;
            int r = idx >> 4, c = idx & 15;
            uint4 v = ((const uint4*)(src + (size_t)r*128))[c];
            *(uint4*)(smem + SM_XN + r*272 + c*16) = v;
        }
    }
    __syncthreads();

    // ---- phase 1: logits = xn @ qk^T (hi + lo) ----
    const int aRow  = (lane & 7) + ((lane >> 3) & 1) * 8;
    const int aKoff = (lane >> 4) * 16;
    {
        const int wbase = wid * 32;
        float c[2][4] = {{0.f,0.f,0.f,0.f},{0.f,0.f,0.f,0.f}};
        const uint32_t bAddrH = sb + SM_QKHI + (lane & 7)*272 + ((lane >> 3) & 1)*16;
        const uint32_t bAddrL = bAddrH + (SM_QKLO - SM_QKHI);
        #pragma unroll
        for (int k = 0; k < 8; k++){
            const uint32_t ko = k*32;
            uint32_t bh0,bh1, bl0,bl1;
            LDSM2(bh0,bh1, bAddrH + ko);
            LDSM2(bl0,bl1, bAddrL + ko);
            #pragma unroll
            for (int mt = 0; mt < 2; mt++){
                uint32_t a0,a1,a2,a3;
                LDSM4(a0,a1,a2,a3, sb + SM_XN + (wbase + mt*16 + aRow)*272 + aKoff + ko);
                MMAF16(c[mt], a0,a1,a2,a3, bh0,bh1);
                MMAF16(c[mt], a0,a1,a2,a3, bl0,bl1);
            }
        }
        #pragma unroll
        for (int mt = 0; mt < 2; mt++){
            const int row = wbase + mt*16 + (lane >> 2);
            const int col = (lane & 3) * 2;
            float2 v0; v0.x = c[mt][0]; v0.y = c[mt][1];
            float2 v1; v1.x = c[mt][2]; v1.y = c[mt][3];
            *(float2*)(smem + SM_LG + row*40 + col*4)     = v0;
            *(float2*)(smem + SM_LG + (row+8)*40 + col*4) = v1;
        }
    }
    __syncthreads();

    // ---- softmax (1 token per thread) -> pA hi/lo ----
    {
        const float* lbs = (const float*)(smem + SM_LB);
        const float* lg = (const float*)(smem + SM_LG + tid*40);
        float l[8];
        #pragma unroll
        for (int i = 0; i < 8; i++) l[i] = lg[i] + lbs[i];
        float mx = l[0];
        #pragma unroll
        for (int i = 1; i < 8; i++) mx = fmaxf(mx, l[i]);
        float sum = 0.f;
        #pragma unroll
        for (int i = 0; i < 8; i++){ l[i] = __expf(l[i]-mx); sum += l[i]; }
        float inv = 1.f/sum;
        #pragma unroll
        for (int i = 0; i < 8; i++){
            float p = l[i]*inv + 1e-8f;
            __half h = __float2half_rn(p);
            __half lo = __float2half_rn(p - __half2float(h));
            *(__half*)(smem + SM_PA + i*528 + tid*2)     = h;
            *(__half*)(smem + SM_PA + (i+8)*528 + tid*2) = lo;
        }
    }
    __syncthreads();

    // ---- rowsum: warp w reduces slot w ----
    {
        const __half2* hi = (const __half2*)(smem + SM_PA + wid*528);
        const __half2* lo = (const __half2*)(smem + SM_PA + (wid+8)*528);
        float r = 0.f;
        #pragma unroll
        for (int i = 0; i < 4; i++){
            float2 a = __half22float2(hi[lane + i*32]);
            float2 b = __half22float2(lo[lane + i*32]);
            r += a.x + a.y + b.x + b.y;
        }
        #pragma unroll
        for (int o = 16; o; o >>= 1) r += __shfl_xor_sync(0xffffffffu, r, o);
        if (lane == 0) atomicAdd(&g_rs[bb*8 + wid], r);
    }

    // ---- phase 2: y = p @ xn  (hi rows 0-7, lo rows 8-15, fold) ----
    {
        float c2[2][4] = {{0.f,0.f,0.f,0.f},{0.f,0.f,0.f,0.f}};
        const uint32_t aBase = sb + SM_PA + aRow*528 + aKoff;
        #pragma unroll
        for (int k = 0; k < 16; k++){
            uint32_t a0,a1,a2,a3;
            LDSM4(a0,a1,a2,a3, aBase + k*32);
            #pragma unroll
            for (int nt = 0; nt < 2; nt++){
                const int d_base = (wid*2 + nt)*8;
                uint32_t b0,b1;
                LDSM2T(b0,b1, sb + SM_XN + (k*16 + (lane & 15))*272 + d_base*2);
                MMAF16(c2[nt], a0,a1,a2,a3, b0,b1);
            }
        }
        const int slot = lane >> 2;
        #pragma unroll
        for (int nt = 0; nt < 2; nt++){
            const int col = (wid*2 + nt)*8 + (lane & 3)*2;
            atomicAdd(&g_y[(bb*8+slot)*128 + col],     c2[nt][0] + c2[nt][2]);
            atomicAdd(&g_y[(bb*8+slot)*128 + col + 1], c2[nt][1] + c2[nt][3]);
        }
    }
}

// ---------------- coalesced 4-row GEMV helper, fp16 weights ----------------
// thread map: r = tid>>2 (output row), q = tid&3 (K quarter, interleaved uint4s)
__device__ __forceinline__ void gemv4h(const __half* __restrict__ W,
                                       const float (* __restrict__ xin)[128],
                                       float* __restrict__ p, int r, int q)
{
    const uint4* w = (const uint4*)(W + r*128);
    p[0] = 0.f; p[1] = 0.f; p[2] = 0.f; p[3] = 0.f;
    #pragma unroll
    for (int e = 0; e < 4; e++){
        uint4 wv = w[q + e*4];
        const __half2* h = (const __half2*)&wv;
        float2 f0 = __half22float2(h[0]);
        float2 f1 = __half22float2(h[1]);
        float2 f2 = __half22float2(h[2]);
        float2 f3 = __half22float2(h[3]);
        #pragma unroll
        for (int j = 0; j < 4; j++){
            const float4* xj = (const float4*)xin[j];
            float4 a = xj[(q + e*4)*2];
            float4 b = xj[(q + e*4)*2 + 1];
            p[j] += f0.x*a.x + f0.y*a.y + f1.x*a.z + f1.y*a.w
                  + f2.x*b.x + f2.y*b.y + f3.x*b.z + f3.y*b.w;
        }
    }
    #pragma unroll
    for (int j = 0; j < 4; j++){
        p[j] += __shfl_xor_sync(0xffffffffu, p[j], 1);
        p[j] += __shfl_xor_sync(0xffffffffu, p[j], 2);
    }
}

// ---------------- kernel 4: GRU+MLP+q, fp16 weights, ILP-ordered ----------------
__global__ __launch_bounds__(512) void gru_mlp_q_kernel(
    const float* __restrict__ b_ih, const float* __restrict__ b_hh,
    const float* __restrict__ gm, const float* __restrict__ bm,
    const float* __restrict__ b1, const float* __restrict__ b2,
    const float* __restrict__ bq,
    const float* __restrict__ gs, const float* __restrict__ bs,
    const float* __restrict__ bv, const float* __restrict__ bk,
    float* __restrict__ out)                     // non-null on final iteration
{
    __shared__ float sx[4][128], sh[4][128], su[4][128], shn[4][128], so[4][128];
    __shared__ float sgi[3][4][128], sgh[3][4][128];
    __shared__ float red_s[4][4], red_ss[4][4];
    const int tid = threadIdx.x;
    const int r  = tid >> 2, q = tid & 3;      // GEMV map
    const int j2 = tid >> 7, d2 = tid & 127;   // pointwise map
    const int lane = tid & 31;
    const int wIn = (tid >> 5) & 3;
    const int r0 = blockIdx.x * 4;

    // ---- head: load y/rs/slots, sync, zero ----
    float yv  = g_y[(r0+j2)*128 + d2];
    float rsv = g_rs[r0+j2];
    float hvv = g_slots[(r0+j2)*128 + d2];
    __syncthreads();
    g_y[(r0+j2)*128 + d2] = 0.f;
    if (tid < 4) g_rs[r0+tid] = 0.f;
    sx[j2][d2] = yv / rsv;
    sh[j2][d2] = hvv;
    __syncthreads();

    float p[4], pg0[4], pg1[4], pg2[4];

    // ---- Stage A: u = Wv@sx AND gh = W_hh@sh (4 independent chunks, 1 sync) ----
    gemv4h(g_wh + WV_OFF,           sx, p,   r, q);
    gemv4h(g_wh + WHH_OFF,          sh, pg0, r, q);
    gemv4h(g_wh + WHH_OFF + 16384,  sh, pg1, r, q);
    gemv4h(g_wh + WHH_OFF + 32768,  sh, pg2, r, q);
    if (q == 0){
        const float b = bv[r];
        const float h0 = b_hh[r], h1 = b_hh[128 + r], h2 = b_hh[256 + r];
        #pragma unroll
        for (int j = 0; j < 4; j++){
            su[j][r]     = b  + p[j];
            sgh[0][j][r] = h0 + pg0[j];
            sgh[1][j][r] = h1 + pg1[j];
            sgh[2][j][r] = h2 + pg2[j];
        }
    }
    __syncthreads();

    // ---- Stage B: gi = W_ih@u (3 independent chunks, 1 sync) ----
    gemv4h(g_wh + WIH_OFF,          su, pg0, r, q);
    gemv4h(g_wh + WIH_OFF + 16384,  su, pg1, r, q);
    gemv4h(g_wh + WIH_OFF + 32768,  su, pg2, r, q);
    if (q == 0){
        const float i0 = b_ih[r], i1 = b_ih[128 + r], i2 = b_ih[256 + r];
        #pragma unroll
        for (int j = 0; j < 4; j++){
            sgi[0][j][r] = i0 + pg0[j];
            sgi[1][j][r] = i1 + pg1[j];
            sgi[2][j][r] = i2 + pg2[j];
        }
    }
    __syncthreads();

    // ---- hn + LN(hn) -> sx ----
    float hn;
    {
        float rr = 1.f/(1.f + __expf(-(sgi[0][j2][d2] + sgh[0][j2][d2])));
        float z  = 1.f/(1.f + __expf(-(sgi[1][j2][d2] + sgh[1][j2][d2])));
        float n  = tanhf(sgi[2][j2][d2] + rr*sgh[2][j2][d2]);
        hn = (1.f - z)*n + z*sh[j2][d2];
        shn[j2][d2] = hn;
        float s = hn, ss = hn*hn;
        #pragma unroll
        for (int o = 16; o; o >>= 1){
            s  += __shfl_xor_sync(0xffffffffu, s, o);
            ss += __shfl_xor_sync(0xffffffffu, ss, o);
        }
        if (lane == 0){ red_s[j2][wIn] = s; red_ss[j2][wIn] = ss; }
    }
    __syncthreads();
    {
        float s  = red_s[j2][0]+red_s[j2][1]+red_s[j2][2]+red_s[j2][3];
        float ss = red_ss[j2][0]+red_ss[j2][1]+red_ss[j2][2]+red_ss[j2][3];
        float m = s*(1.f/128.f);
        float rstd = rsqrtf(ss*(1.f/128.f) - m*m + 1e-5f);
        sx[j2][d2] = (hn - m)*rstd*gm[d2] + bm[d2];
    }
    __syncthreads();

    // ---- MLP layer 1 (relu) -> su ----
    gemv4h(g_wh + W1_OFF, sx, p, r, q);
    if (q == 0){
        const float b = b1[r];
        #pragma unroll
        for (int j = 0; j < 4; j++) su[j][r] = fmaxf(b + p[j], 0.f);
    }
    __syncthreads();

    // ---- MLP layer 2 + residual -> so, g_slots (and d_out on final iter) ----
    gemv4h(g_wh + W2_OFF, su, p, r, q);
    if (q == 0){
        const float b = b2[r];
        #pragma unroll
        for (int j = 0; j < 4; j++){
            float o = shn[j][r] + b + p[j];
            so[j][r] = o;
            g_slots[(r0+j)*128 + r] = o;
            if (out) out[(r0+j)*128 + r] = o;
        }
    }
    __syncthreads();

    // ---- LN(out) -> sx ----
    float ov = so[j2][d2];
    {
        float s = ov, ss = ov*ov;
        #pragma unroll
        for (int o = 16; o; o >>= 1){
            s  += __shfl_xor_sync(0xffffffffu, s, o);
            ss += __shfl_xor_sync(0xffffffffu, ss, o);
        }
        if (lane == 0){ red_s[j2][wIn] = s; red_ss[j2][wIn] = ss; }
    }
    __syncthreads();
    {
        float s  = red_s[j2][0]+red_s[j2][1]+red_s[j2][2]+red_s[j2][3];
        float ss = red_ss[j2][0]+red_ss[j2][1]+red_ss[j2][2]+red_ss[j2][3];
        float m = s*(1.f/128.f);
        float rstd = rsqrtf(ss*(1.f/128.f) - m*m + 1e-5f);
        sx[j2][d2] = (ov - m)*rstd*gs[d2] + bs[d2];
    }
    __syncthreads();

    // ---- q projection (scaled) -> su ----
    gemv4h(g_wh + WQ_OFF, sx, p, r, q);
    if (q == 0){
        const float b = bq[r];
        #pragma unroll
        for (int j = 0; j < 4; j++) su[j][r] = (b + p[j]) * SCALE;
    }
    __syncthreads();

    // ---- qk = sq @ Wk (via wkT) ; lb = sq . bk ----
    gemv4h(g_wh + WKT_OFF, su, p, r, q);
    if (q == 0){
        #pragma unroll
        for (int j = 0; j < 4; j++) g_qk[(r0+j)*128 + r] = p[j];
    }
    {
        float pb = su[j2][d2] * bk[d2];
        #pragma unroll
        for (int o = 16; o; o >>= 1) pb += __shfl_xor_sync(0xffffffffu, pb, o);
        if (lane == 0) red_s[j2][wIn] = pb;
    }
    __syncthreads();
    if (tid < 4)
        g_lb[r0 + tid] = red_s[tid][0]+red_s[tid][1]+red_s[tid][2]+red_s[tid][3];
}

// ---------------- launch ----------------
extern "C" void kernel_launch(void* const* d_in, const int* in_sizes, int n_in,
                              void* d_out, int out_size)
{
    const float* x    = (const float*)d_in[0];
    const float* si   = (const float*)d_in[1];
    const float* Wq   = (const float*)d_in[2];
    const float* bq   = (const float*)d_in[3];
    const float* Wk   = (const float*)d_in[4];
    const float* bk   = (const float*)d_in[5];
    const float* Wv   = (const float*)d_in[6];
    const float* bv   = (const float*)d_in[7];
    const float* gin  = (const float*)d_in[8];
    const float* bin  = (const float*)d_in[9];
    const float* gsl  = (const float*)d_in[10];
    const float* bsl  = (const float*)d_in[11];
    const float* gm   = (const float*)d_in[12];
    const float* bm   = (const float*)d_in[13];
    const float* W1   = (const float*)d_in[14];
    const float* b1   = (const float*)d_in[15];
    const float* W2   = (const float*)d_in[16];
    const float* b2   = (const float*)d_in[17];
    const float* W_ih = (const float*)d_in[18];
    const float* W_hh = (const float*)d_in[19];
    const float* b_ih = (const float*)d_in[20];
    const float* b_hh = (const float*)d_in[21];

    static bool attr_set = false;
    if (!attr_set){
        cudaFuncSetAttribute(fused_attn_mma_kernel,
                             cudaFuncAttributeMaxDynamicSharedMemorySize, SM_TOT);
        attr_set = true;
    }

    prep_weights_kernel<<<704, 256>>>(Wk, Wv, W_hh, W_ih, W1, W2, Wq);
    init_q_kernel<<<512, 128>>>(si, Wq, bq, gsl, bsl, bk);
    for (int it = 0; it < 3; it++){
        fused_attn_mma_kernel<<<1024, 256, SM_TOT>>>(
            it == 0 ? x : nullptr, gin, bin);
        gru_mlp_q_kernel<<<128, 512>>>(b_ih, b_hh, gm, bm, b1, b2,
                                       bq, gsl, bsl, bv, bk,
                                       it == 2 ? (float*)d_out : nullptr);
    }
}